// round 16
// baseline (speedup 1.0000x reference)
#include <cuda_runtime.h>
#include <cuda_fp16.h>
#include <math.h>
#include <cstdint>

// Problem constants
#define BB 4
#define SS 4096
#define DD 1024
#define HH 16
#define DH 64
#define MM (BB * SS)          // 16384 rows
#define CC 64                 // chunk length
#define NC (SS / CC)          // 64 chunks per sequence
#define EPS 1e-6f

// ---------------------------------------------------------------------------
// Scratch (device globals; no allocation allowed)
// ---------------------------------------------------------------------------
__device__ __align__(256) __half g_xhi[(size_t)MM * DD];
__device__ __align__(256) __half g_qh[(size_t)MM * DD];
__device__ __align__(256) __half g_kh[(size_t)MM * DD];
__device__ __align__(256) __half g_vh[(size_t)MM * DD];
__device__ __align__(256) __half g_ahi[(size_t)MM * DD];
__device__ __align__(256) __half g_wt[4][(size_t)DD * DD];
// chunk states: raw sums fp32, exclusive-prefixed fp16 hi/lo
__device__ __align__(256) float  g_cS[(size_t)BB * HH * NC * DH * DH];
__device__ __align__(256) __half g_Shi[(size_t)BB * HH * NC * DH * DH];
__device__ __align__(256) __half g_Slo[(size_t)BB * HH * NC * DH * DH];
__device__ __align__(256) float  g_cz[(size_t)BB * HH * NC * DH];

// ---------------------------------------------------------------------------
// Warp-MMA + cp.async helpers
// ---------------------------------------------------------------------------
__device__ __forceinline__ uint32_t smem_u32(const void* p) {
    uint32_t a;
    asm("{ .reg .u64 t; cvta.to.shared.u64 t, %1; cvt.u32.u64 %0, t; }"
        : "=r"(a) : "l"(p));
    return a;
}
__device__ __forceinline__ void ldsm_x4(uint32_t* r, uint32_t addr) {
    asm volatile("ldmatrix.sync.aligned.m8n8.x4.shared.b16 {%0,%1,%2,%3}, [%4];"
                 : "=r"(r[0]), "=r"(r[1]), "=r"(r[2]), "=r"(r[3]) : "r"(addr));
}
__device__ __forceinline__ void ldsm_x4_t(uint32_t* r, uint32_t addr) {
    asm volatile("ldmatrix.sync.aligned.m8n8.x4.trans.shared.b16 {%0,%1,%2,%3}, [%4];"
                 : "=r"(r[0]), "=r"(r[1]), "=r"(r[2]), "=r"(r[3]) : "r"(addr));
}
__device__ __forceinline__ void mma_fp16(float* d, const uint32_t* a,
                                         uint32_t b0, uint32_t b1) {
    asm volatile(
        "mma.sync.aligned.m16n8k16.row.col.f32.f16.f16.f32 "
        "{%0,%1,%2,%3}, {%4,%5,%6,%7}, {%8,%9}, {%0,%1,%2,%3};"
        : "+f"(d[0]), "+f"(d[1]), "+f"(d[2]), "+f"(d[3])
        : "r"(a[0]), "r"(a[1]), "r"(a[2]), "r"(a[3]), "r"(b0), "r"(b1));
}
__device__ __forceinline__ void cpa16(uint32_t dst, const void* src) {
    asm volatile("cp.async.cg.shared.global [%0], [%1], 16;"
                 :: "r"(dst), "l"(src));
}
#define CP_COMMIT() asm volatile("cp.async.commit_group;" ::: "memory")
#define CP_WAIT1()  asm volatile("cp.async.wait_group 1;" ::: "memory")
#define CP_WAIT0()  asm volatile("cp.async.wait_group 0;" ::: "memory")

// ---------------------------------------------------------------------------
// Pipelined mma.sync fp16 GEMM, SINGLE pass, BK=64 (16 chunks, half the
// barriers of BK=32 — tests the sync-overhead theory of the 51% tensor cap).
// CTA 128x128, 16 warps (4x4), warp tile 32x32, 2-stage cp.async.
// outmode 1: write q/k/v fp16 with phi on q,k.  outmode 0: fp32 to cf.
// ---------------------------------------------------------------------------
#define GBK 64
#define NKCH (DD / GBK)       // 16
#define GSTR 72               // padded smem row stride (halfs), 64 + 8
#define GSTG (128 * GSTR)     // halfs per tile buffer (9216)
#define GEMM_SMEM (2 * 2 * GSTG * 2)   // 2 stages x 2 tiles x 18432 B = 73728

__global__ __launch_bounds__(512, 1) void gemm_mma(const __half* __restrict__ Ah,
                                                   const __half* __restrict__ Bw,
                                                   __half* __restrict__ oq,
                                                   __half* __restrict__ ok,
                                                   __half* __restrict__ ov,
                                                   float* __restrict__ cf, int outmode) {
    extern __shared__ __half smbuf[];
    uint32_t bsm = smem_u32(smbuf);

    int tid  = threadIdx.x;
    int wid  = tid >> 5;
    int lane = tid & 31;
    int wr   = wid >> 2;
    int wc   = wid & 3;
    int m0   = blockIdx.y * 128;
    int n0   = blockIdx.x * 128;

    // per-thread load coords: TWO 16B chunks per tile per stage
    // (128 rows x 64 halfs = 1024 x 16B ; 512 threads x 2 reps)
    int r0c = (tid + 0)   >> 3, s0c = ((tid + 0)   & 7) * 8;
    int r1c = (tid + 512) >> 3, s1c = ((tid + 512) & 7) * 8;
    uint32_t off0 = (uint32_t)(r0c * GSTR + s0c) * 2;
    uint32_t off1 = (uint32_t)(r1c * GSTR + s1c) * 2;

    const __half* gA0 = Ah + (size_t)(m0 + r0c) * DD + s0c;
    const __half* gA1 = Ah + (size_t)(m0 + r1c) * DD + s1c;
    const __half* gB0 = Bw + (size_t)(n0 + r0c) * DD + s0c;
    const __half* gB1 = Bw + (size_t)(n0 + r1c) * DD + s1c;

    auto issue = [&](int ch, int s) {
        int k0 = ch * GBK;
        uint32_t base = bsm + (uint32_t)(s * 2) * (uint32_t)(GSTG * 2);
        cpa16(base + off0, gA0 + k0);
        cpa16(base + off1, gA1 + k0);
        cpa16(base + GSTG * 2 + off0, gB0 + k0);
        cpa16(base + GSTG * 2 + off1, gB1 + k0);
    };

    float acc[2][4][4];
#pragma unroll
    for (int i = 0; i < 2; ++i)
#pragma unroll
        for (int j = 0; j < 4; ++j)
#pragma unroll
            for (int r = 0; r < 4; ++r) acc[i][j][r] = 0.f;

    uint32_t aRow = wr * 32 + (lane & 15);
    uint32_t aCol = (lane >> 4) * 8;
    uint32_t bRow = wc * 32 + (lane & 7);
    uint32_t bCol = (lane >> 3) * 8;

    issue(0, 0); CP_COMMIT();
    issue(1, 1); CP_COMMIT();

    int cur = 0;
    for (int ch = 0; ch < NKCH; ++ch) {
        CP_WAIT1();
        __syncthreads();

        uint32_t base = bsm + (uint32_t)(cur * 2) * (uint32_t)(GSTG * 2);
        uint32_t bA = base, bB = base + GSTG * 2;

#pragma unroll
        for (int half = 0; half < 2; ++half) {      // two 32-k blocks
            uint32_t fb[4][4];
#pragma unroll
            for (int nt = 0; nt < 4; ++nt)
                ldsm_x4(fb[nt], bB + ((bRow + nt * 8) * GSTR + half * 32 + bCol) * 2);
#pragma unroll
            for (int ks = 0; ks < 2; ++ks) {
                uint32_t fa[2][4];
#pragma unroll
                for (int mt = 0; mt < 2; ++mt)
                    ldsm_x4(fa[mt], bA + ((aRow + mt * 16) * GSTR + half * 32 + ks * 16 + aCol) * 2);
#pragma unroll
                for (int mt = 0; mt < 2; ++mt)
#pragma unroll
                    for (int nt = 0; nt < 4; ++nt)
                        mma_fp16(acc[mt][nt], fa[mt], fb[nt][ks * 2], fb[nt][ks * 2 + 1]);
            }
        }
        __syncthreads();
        if (ch + 2 < NKCH) issue(ch + 2, cur);
        CP_COMMIT();
        cur ^= 1;
    }

    int which = n0 >> 10;
    int ncol  = n0 & 1023;
    int erow  = m0 + wr * 32 + (lane >> 2);
    int ecol  = ncol + wc * 32 + (lane & 3) * 2;

    if (outmode) {
        __half* oh = (which == 0) ? oq : ((which == 1) ? ok : ov);
        int phi = (which != 2);
#pragma unroll
        for (int mt = 0; mt < 2; ++mt) {
#pragma unroll
            for (int nt = 0; nt < 4; ++nt) {
                float v0 = acc[mt][nt][0], v1 = acc[mt][nt][1];
                float v2 = acc[mt][nt][2], v3 = acc[mt][nt][3];
                if (phi) {
                    v0 = (v0 > 0.f) ? (v0 + 1.f) : expf(v0);
                    v1 = (v1 > 0.f) ? (v1 + 1.f) : expf(v1);
                    v2 = (v2 > 0.f) ? (v2 + 1.f) : expf(v2);
                    v3 = (v3 > 0.f) ? (v3 + 1.f) : expf(v3);
                }
                size_t p0 = (size_t)(erow + mt * 16) * DD + ecol + nt * 8;
                size_t p1 = (size_t)(erow + mt * 16 + 8) * DD + ecol + nt * 8;
                *(__half2*)&oh[p0] = __half2(__float2half(v0), __float2half(v1));
                *(__half2*)&oh[p1] = __half2(__float2half(v2), __float2half(v3));
            }
        }
    } else {
#pragma unroll
        for (int mt = 0; mt < 2; ++mt) {
#pragma unroll
            for (int nt = 0; nt < 4; ++nt) {
                float* p0 = cf + (size_t)(erow + mt * 16) * DD + ecol + nt * 8;
                float* p1 = cf + (size_t)(erow + mt * 16 + 8) * DD + ecol + nt * 8;
                *(float2*)p0 = make_float2(acc[mt][nt][0], acc[mt][nt][1]);
                *(float2*)p1 = make_float2(acc[mt][nt][2], acc[mt][nt][3]);
            }
        }
    }
}

// ---------------------------------------------------------------------------
// x -> fp16: 8 elements/thread, 2 independent float4 loads (MLP=2)
// ---------------------------------------------------------------------------
__global__ __launch_bounds__(256) void convert_x(const float* __restrict__ x,
                                                 __half* __restrict__ hi) {
    size_t i8 = ((size_t)blockIdx.x * 256 + threadIdx.x) * 8;
    float4 a = *(const float4*)(x + i8);
    float4 b = *(const float4*)(x + i8 + 4);
    *(__half2*)(hi + i8)     = __half2(__float2half(a.x), __float2half(a.y));
    *(__half2*)(hi + i8 + 2) = __half2(__float2half(a.z), __float2half(a.w));
    *(__half2*)(hi + i8 + 4) = __half2(__float2half(b.x), __float2half(b.y));
    *(__half2*)(hi + i8 + 6) = __half2(__float2half(b.z), __float2half(b.w));
}

// ---------------------------------------------------------------------------
// All 4 weights: W [K,N] fp32 -> Wt [N,K] fp16
// ---------------------------------------------------------------------------
__global__ __launch_bounds__(256) void wconv_all(const float* __restrict__ W0,
                                                 const float* __restrict__ W1,
                                                 const float* __restrict__ W2,
                                                 const float* __restrict__ W3,
                                                 __half* __restrict__ WtB) {
    __shared__ float ts[32][33];
    int z = blockIdx.z;
    const float* W = (z == 0) ? W0 : (z == 1) ? W1 : (z == 2) ? W2 : W3;
    __half* Wt = WtB + (size_t)z * DD * DD;
    int n0 = blockIdx.x * 32, k0 = blockIdx.y * 32;
    int tx = threadIdx.x, ty = threadIdx.y;
#pragma unroll
    for (int j = 0; j < 4; ++j)
        ts[ty + j * 8][tx] = W[(size_t)(k0 + ty + j * 8) * DD + n0 + tx];
    __syncthreads();
#pragma unroll
    for (int j = 0; j < 4; ++j)
        Wt[(size_t)(n0 + ty + j * 8) * DD + k0 + tx] = __float2half(ts[tx][ty + j * 8]);
}

// ---------------------------------------------------------------------------
// chunk_mma: cS[bid] = K^T V (fp16 inputs exact, 1-pass), cz[bid] = colsum(K).
// ---------------------------------------------------------------------------
#define TSTR 72
#define ITILE (64 * TSTR)

__global__ __launch_bounds__(256) void chunk_mma(const __half* __restrict__ kh,
                                                 const __half* __restrict__ vh,
                                                 float* __restrict__ cS,
                                                 float* __restrict__ cz) {
    __shared__ __half tk[ITILE], tv[ITILE];

    int bid = blockIdx.x, bh = bid >> 6, c = bid & 63, b = bh >> 4, h = bh & 15;
    int tid = threadIdx.x, wid = tid >> 5, lane = tid & 31;
    int wr = wid >> 2, wc = wid & 3;

    size_t mrow = (size_t)(b * SS + c * CC);
    uint32_t kb = smem_u32(tk), vb = smem_u32(tv);
#pragma unroll
    for (int rep = 0; rep < 2; ++rep) {
        int u = tid + rep * 256;
        int row = u >> 3, seg = u & 7;
        cpa16(kb + (uint32_t)(row * TSTR + seg * 8) * 2,
              kh + (mrow + row) * DD + h * DH + seg * 8);
        cpa16(vb + (uint32_t)(row * TSTR + seg * 8) * 2,
              vh + (mrow + row) * DD + h * DH + seg * 8);
    }
    CP_COMMIT(); CP_WAIT0();
    __syncthreads();

    float acc[2][2][4];
#pragma unroll
    for (int i = 0; i < 2; ++i)
#pragma unroll
        for (int j = 0; j < 2; ++j)
#pragma unroll
            for (int r = 0; r < 4; ++r) acc[i][j][r] = 0.f;

    uint32_t taR = (lane & 7) + ((lane >> 4) << 3);
    uint32_t taC = ((lane >> 3) & 1) << 3;
    uint32_t tbR = (lane & 7) + (((lane >> 3) & 1) << 3);
    uint32_t tbC = (lane >> 4) * 8;

#pragma unroll
    for (int kc = 0; kc < 4; ++kc) {
        uint32_t fb[4];
        ldsm_x4_t(fb, vb + ((kc * 16 + tbR) * TSTR + wc * 16 + tbC) * 2);
        uint32_t fa[2][4];
#pragma unroll
        for (int mt = 0; mt < 2; ++mt)
            ldsm_x4_t(fa[mt], kb + ((kc * 16 + taR) * TSTR + wr * 32 + mt * 16 + taC) * 2);
#pragma unroll
        for (int mt = 0; mt < 2; ++mt)
#pragma unroll
            for (int nt = 0; nt < 2; ++nt)
                mma_fp16(acc[mt][nt], fa[mt], fb[nt * 2], fb[nt * 2 + 1]);
    }

    int er = wr * 32 + (lane >> 2);
    int ec = wc * 16 + 2 * (lane & 3);
    float* outp = cS + (size_t)bid * 4096;
#pragma unroll
    for (int mt = 0; mt < 2; ++mt)
#pragma unroll
        for (int nt = 0; nt < 2; ++nt) {
            int r = er + mt * 16, cc2 = ec + nt * 8;
            *(float2*)&outp[(r)     * 64 + cc2] = make_float2(acc[mt][nt][0], acc[mt][nt][1]);
            *(float2*)&outp[(r + 8) * 64 + cc2] = make_float2(acc[mt][nt][2], acc[mt][nt][3]);
        }

    if (tid < 64) {
        float z = 0.f;
        for (int t = 0; t < 64; ++t) z += __half2float(tk[t * TSTR + tid]);
        cz[(size_t)bid * 64 + tid] = z;
    }
}

// ---------------------------------------------------------------------------
// prefix: exclusive prefix over chunks (seeded by cache); S out as fp16 hi/lo.
// ---------------------------------------------------------------------------
__global__ __launch_bounds__(256) void prefix_kernel(const float* __restrict__ cache,
                                                     const float* __restrict__ cS,
                                                     __half* __restrict__ Shi,
                                                     __half* __restrict__ Slo,
                                                     float* __restrict__ cz) {
    int bh = blockIdx.x;
    int f  = blockIdx.y * 256 + threadIdx.x;
    int d = f >> 6, e = f & 63;
    float run = cache[((size_t)bh * 65 + d) * 64 + e];

    for (int c = 0; c < NC; ++c) {
        size_t a = ((size_t)(bh * NC + c)) * 4096 + f;
        float t = cS[a];
        __half hp = __float2half(run);
        Shi[a] = hp;
        Slo[a] = __float2half(run - __half2float(hp));
        run += t;
    }
    if (blockIdx.y == 0 && threadIdx.x < 64) {
        int dz = threadIdx.x;
        float rz = cache[((size_t)bh * 65 + 64) * 64 + dz];
        for (int c = 0; c < NC; ++c) {
            size_t a = ((size_t)(bh * NC + c)) * 64 + dz;
            float t = cz[a];
            cz[a] = rz;
            rz += t;
        }
    }
}

// ---------------------------------------------------------------------------
// intra_mma: out = (Q@S_start + mask(QK^T)@V) / (q.z + rowsumA + eps)
// ---------------------------------------------------------------------------
#define INTRA_SMEM (6 * ITILE * 2 + 3 * 64 * 4)

__global__ __launch_bounds__(256) void intra_mma(const __half* __restrict__ qh,
                                                 const __half* __restrict__ kh,
                                                 const __half* __restrict__ vh,
                                                 const __half* __restrict__ Shg,
                                                 const __half* __restrict__ Slg,
                                                 const float* __restrict__ cz,
                                                 __half* __restrict__ ahi) {
    extern __shared__ __half ism[];
    __half* tq   = ism;
    __half* tk   = ism + ITILE;       // reused as A_hi after QK^T
    __half* tv   = ism + 2 * ITILE;
    __half* tS_h = ism + 3 * ITILE;
    __half* tS_l = ism + 4 * ITILE;
    __half* tA_l = ism + 5 * ITILE;
    float* s_z   = (float*)(ism + 6 * ITILE);
    float* s_den = s_z + 64;
    float* s_inv = s_den + 64;
    __half* tA_h = tk;

    int bid = blockIdx.x, bh = bid >> 6, c = bid & 63, b = bh >> 4, h = bh & 15;
    int tid = threadIdx.x, wid = tid >> 5, lane = tid & 31;
    int wr = wid >> 2, wc = wid & 3;

    size_t mrow = (size_t)(b * SS + c * CC);
    {
        const __half* src[3] = {qh, kh, vh};
        __half* dst[3] = {tq, tk, tv};
#pragma unroll
        for (int t = 0; t < 3; ++t) {
            uint32_t db = smem_u32(dst[t]);
#pragma unroll
            for (int rep = 0; rep < 2; ++rep) {
                int u = tid + rep * 256;
                int row = u >> 3, seg = u & 7;
                cpa16(db + (uint32_t)(row * TSTR + seg * 8) * 2,
                      src[t] + (mrow + row) * DD + h * DH + seg * 8);
            }
        }
        uint32_t dh = smem_u32(tS_h), dl = smem_u32(tS_l);
#pragma unroll
        for (int rep = 0; rep < 2; ++rep) {
            int u = tid + rep * 256;
            int row = u >> 3, seg = u & 7;
            cpa16(dh + (uint32_t)(row * TSTR + seg * 8) * 2,
                  Shg + (size_t)bid * 4096 + u * 8);
            cpa16(dl + (uint32_t)(row * TSTR + seg * 8) * 2,
                  Slg + (size_t)bid * 4096 + u * 8);
        }
    }
    if (tid < 64) s_z[tid] = cz[(size_t)bid * 64 + tid];
    CP_COMMIT(); CP_WAIT0();
    __syncthreads();

    // den init = q . z
    {
        int i = tid >> 2, l4 = tid & 3;
        float a = 0.f;
        for (int d = l4 * 16; d < l4 * 16 + 16; ++d)
            a += __half2float(tq[i * TSTR + d]) * s_z[d];
        a += __shfl_xor_sync(0xffffffffu, a, 1);
        a += __shfl_xor_sync(0xffffffffu, a, 2);
        if (l4 == 0) s_den[i] = a;
    }
    __syncthreads();

    uint32_t qb = smem_u32(tq), kb = smem_u32(tk), vb = smem_u32(tv);
    uint32_t sbh = smem_u32(tS_h), sbl = smem_u32(tS_l);
    uint32_t abh = smem_u32(tA_h), abl = smem_u32(tA_l);

    uint32_t aRow = wr * 32 + (lane & 15);
    uint32_t aCol = (lane >> 4) * 8;
    uint32_t bRowN = wc * 16 + (lane & 7);
    uint32_t bColN = (lane >> 3) * 8;
    uint32_t tbR = (lane & 7) + (((lane >> 3) & 1) << 3);
    uint32_t tbC = (lane >> 4) * 8;

    // ---- QK^T 1-pass (exact fp16 inputs) ----
    float fA[2][2][4];
#pragma unroll
    for (int i = 0; i < 2; ++i)
#pragma unroll
        for (int j = 0; j < 2; ++j)
#pragma unroll
            for (int r = 0; r < 4; ++r) fA[i][j][r] = 0.f;

#pragma unroll
    for (int kc = 0; kc < 2; ++kc) {
        uint32_t fb[2][4];
#pragma unroll
        for (int nt = 0; nt < 2; ++nt)
            ldsm_x4(fb[nt], kb + ((bRowN + nt * 8) * TSTR + kc * 32 + bColN) * 2);
#pragma unroll
        for (int ks = 0; ks < 2; ++ks) {
            uint32_t fa[2][4];
#pragma unroll
            for (int mt = 0; mt < 2; ++mt)
                ldsm_x4(fa[mt], qb + ((aRow + mt * 16) * TSTR + kc * 32 + ks * 16 + aCol) * 2);
#pragma unroll
            for (int mt = 0; mt < 2; ++mt)
#pragma unroll
                for (int nt = 0; nt < 2; ++nt)
                    mma_fp16(fA[mt][nt], fa[mt], fb[nt][ks * 2], fb[nt][ks * 2 + 1]);
        }
    }

    // mask + rowsum
    int r0 = wr * 32 + (lane >> 2);
    int c0 = wc * 16 + 2 * (lane & 3);
#pragma unroll
    for (int mt = 0; mt < 2; ++mt) {
        float rsA = 0.f, rsB = 0.f;
#pragma unroll
        for (int nt = 0; nt < 2; ++nt) {
            int i0 = r0 + mt * 16, i1 = i0 + 8;
            int j0 = c0 + nt * 8, j1 = j0 + 1;
            if (j0 > i0) fA[mt][nt][0] = 0.f;
            if (j1 > i0) fA[mt][nt][1] = 0.f;
            if (j0 > i1) fA[mt][nt][2] = 0.f;
            if (j1 > i1) fA[mt][nt][3] = 0.f;
            rsA += fA[mt][nt][0] + fA[mt][nt][1];
            rsB += fA[mt][nt][2] + fA[mt][nt][3];
        }
        rsA += __shfl_xor_sync(0xffffffffu, rsA, 1);
        rsA += __shfl_xor_sync(0xffffffffu, rsA, 2);
        rsB += __shfl_xor_sync(0xffffffffu, rsB, 1);
        rsB += __shfl_xor_sync(0xffffffffu, rsB, 2);
        if ((lane & 3) == 0) {
            atomicAdd(&s_den[r0 + mt * 16], rsA);
            atomicAdd(&s_den[r0 + mt * 16 + 8], rsB);
        }
    }
    __syncthreads();   // atomics done; k tile fragments consumed

    // store masked A hi/lo (A_hi overwrites k tile)
#pragma unroll
    for (int mt = 0; mt < 2; ++mt)
#pragma unroll
        for (int nt = 0; nt < 2; ++nt) {
            int i0 = r0 + mt * 16, i1 = i0 + 8, j0 = c0 + nt * 8;
            float v0 = fA[mt][nt][0], v1 = fA[mt][nt][1];
            float v2 = fA[mt][nt][2], v3 = fA[mt][nt][3];
            __half h0 = __float2half(v0), h1 = __float2half(v1);
            __half h2 = __float2half(v2), h3 = __float2half(v3);
            *(__half2*)&tA_h[i0 * TSTR + j0] = __half2(h0, h1);
            *(__half2*)&tA_h[i1 * TSTR + j0] = __half2(h2, h3);
            *(__half2*)&tA_l[i0 * TSTR + j0] =
                __half2(__float2half(v0 - __half2float(h0)), __float2half(v1 - __half2float(h1)));
            *(__half2*)&tA_l[i1 * TSTR + j0] =
                __half2(__float2half(v2 - __half2float(h2)), __float2half(v3 - __half2float(h3)));
        }
    if (tid < 64) s_inv[tid] = 1.f / (s_den[tid] + EPS);
    __syncthreads();

    // ---- out = Q@S (2-pass S hi/lo) + A@V (2-pass A hi/lo) ----
    float fO[2][2][4];
#pragma unroll
    for (int i = 0; i < 2; ++i)
#pragma unroll
        for (int j = 0; j < 2; ++j)
#pragma unroll
            for (int r = 0; r < 4; ++r) fO[i][j][r] = 0.f;

#pragma unroll
    for (int kc = 0; kc < 4; ++kc) {
        uint32_t ob = ((kc * 16 + tbR) * TSTR + wc * 16 + tbC) * 2;
        uint32_t gsh[4], gsl[4], gv[4];
        ldsm_x4_t(gsh, sbh + ob);
        ldsm_x4_t(gsl, sbl + ob);
        ldsm_x4_t(gv,  vb  + ob);
        uint32_t fq[2][4], fxh[2][4], fxl[2][4];
#pragma unroll
        for (int mt = 0; mt < 2; ++mt) {
            uint32_t oa = ((aRow + mt * 16) * TSTR + kc * 16 + aCol) * 2;
            ldsm_x4(fq[mt],  qb  + oa);
            ldsm_x4(fxh[mt], abh + oa);
            ldsm_x4(fxl[mt], abl + oa);
        }
#pragma unroll
        for (int mt = 0; mt < 2; ++mt)
#pragma unroll
            for (int nt = 0; nt < 2; ++nt) {
                mma_fp16(fO[mt][nt], fq[mt],  gsh[nt * 2], gsh[nt * 2 + 1]);
                mma_fp16(fO[mt][nt], fq[mt],  gsl[nt * 2], gsl[nt * 2 + 1]);
                mma_fp16(fO[mt][nt], fxh[mt], gv[nt * 2],  gv[nt * 2 + 1]);
                mma_fp16(fO[mt][nt], fxl[mt], gv[nt * 2],  gv[nt * 2 + 1]);
            }
    }

    // scale by 1/den, store fp16
#pragma unroll
    for (int mt = 0; mt < 2; ++mt) {
        float inv0 = s_inv[r0 + mt * 16];
        float inv1 = s_inv[r0 + mt * 16 + 8];
#pragma unroll
        for (int nt = 0; nt < 2; ++nt) {
            float v0 = fO[mt][nt][0] * inv0, v1 = fO[mt][nt][1] * inv0;
            float v2 = fO[mt][nt][2] * inv1, v3 = fO[mt][nt][3] * inv1;
            size_t m0g = mrow + r0 + mt * 16;
            size_t col = (size_t)h * DH + c0 + nt * 8;
            *(__half2*)&ahi[m0g * DD + col] =
                __half2(__float2half(v0), __float2half(v1));
            *(__half2*)&ahi[(m0g + 8) * DD + col] =
                __half2(__float2half(v2), __float2half(v3));
        }
    }
}

// ---------------------------------------------------------------------------
// Launch
// ---------------------------------------------------------------------------
extern "C" void kernel_launch(void* const* d_in, const int* in_sizes, int n_in,
                              void* d_out, int out_size) {
    const float* x     = (const float*)d_in[0];
    const float* cache = (const float*)d_in[1];
    const float* Wq    = (const float*)d_in[2];
    const float* Wk    = (const float*)d_in[3];
    const float* Wv    = (const float*)d_in[4];
    const float* Wo    = (const float*)d_in[5];
    float* out = (float*)d_out;

    __half *xhi, *qh, *kh, *vh, *ahi, *wt, *Shi, *Slo;
    float *cSp, *czp;
    cudaGetSymbolAddress((void**)&xhi, g_xhi);
    cudaGetSymbolAddress((void**)&qh,  g_qh);
    cudaGetSymbolAddress((void**)&kh,  g_kh);
    cudaGetSymbolAddress((void**)&vh,  g_vh);
    cudaGetSymbolAddress((void**)&ahi, g_ahi);
    cudaGetSymbolAddress((void**)&wt,  g_wt);
    cudaGetSymbolAddress((void**)&Shi, g_Shi);
    cudaGetSymbolAddress((void**)&Slo, g_Slo);
    cudaGetSymbolAddress((void**)&cSp, g_cS);
    cudaGetSymbolAddress((void**)&czp, g_cz);

    cudaFuncSetAttribute(gemm_mma, cudaFuncAttributeMaxDynamicSharedMemorySize, GEMM_SMEM);
    cudaFuncSetAttribute(intra_mma, cudaFuncAttributeMaxDynamicSharedMemorySize, INTRA_SMEM);

    const size_t WSTRIDE = (size_t)DD * DD;

    wconv_all<<<dim3(32, 32, 4), dim3(32, 8)>>>(Wq, Wk, Wv, Wo, wt);
    convert_x<<<MM * DD / 2048, 256>>>(x, xhi);

    // Fused QKV GEMM (1-pass fp16, BK=64)
    gemm_mma<<<dim3(24, 128), 512, GEMM_SMEM>>>(xhi, wt, qh, kh, vh, out, 1);

    chunk_mma<<<BB * HH * NC, 256>>>(kh, vh, cSp, czp);
    prefix_kernel<<<dim3(BB * HH, 16), 256>>>(cache, cSp, Shi, Slo, czp);
    intra_mma<<<BB * HH * NC, 256, INTRA_SMEM>>>(qh, kh, vh, Shi, Slo, czp, ahi);

    // Wo GEMM (1-pass fp16, BK=64)
    gemm_mma<<<dim3(8, 128), 512, GEMM_SMEM>>>(ahi, wt + 3 * WSTRIDE,
                                               qh, kh, vh, out, 0);
}